// round 4
// baseline (speedup 1.0000x reference)
#include <cuda_runtime.h>
#include <cstdint>

#define N_ATOMS  200000
#define N_FEAT   1024
#define N_STRUCT 2000
#define NTHREADS 512
#define M_TILE   128
#define CHUNKS1  32
#define CHUNKS2  8

// ---- SMEM layout (bytes) ----
#define OFF_B      0        // 3 x 32768 B-operand stream bufs
#define OFF_A      98304    // 2 x 16384 A-operand bufs (GEMM1)
#define OFF_H1     98304    // 8 x 16384 h1 fragment chunks (aliases A bufs, used after GEMM1)
#define OFF_WOUT   229376   // 1024
#define OFF_SATOM  230400   // 512
#define SMEM_BYTES 230912

// weights pre-packed into mma fragment layout (tf32)
__device__ __align__(16) uint32_t g_W1p[256 * 1024];
__device__ __align__(16) uint32_t g_W2p[256 * 256];

__device__ __forceinline__ uint32_t cvt_tf32(float x) {
    uint32_t r;
    asm("cvt.rna.tf32.f32 %0, %1;" : "=r"(r) : "f"(x));
    return r;
}

__device__ __forceinline__ void mma_tf32(float c[4], const uint32_t a[4], const uint32_t b[2]) {
    asm volatile(
        "mma.sync.aligned.m16n8k8.row.col.f32.tf32.tf32.f32 "
        "{%0,%1,%2,%3}, {%4,%5,%6,%7}, {%8,%9}, {%0,%1,%2,%3};\n"
        : "+f"(c[0]), "+f"(c[1]), "+f"(c[2]), "+f"(c[3])
        : "r"(a[0]), "r"(a[1]), "r"(a[2]), "r"(a[3]), "r"(b[0]), "r"(b[1]));
}

__device__ __forceinline__ void cp_async16(uint32_t saddr, const void* gptr) {
    asm volatile("cp.async.cg.shared.global [%0], [%1], 16;\n" :: "r"(saddr), "l"(gptr));
}
__device__ __forceinline__ void cp_commit() { asm volatile("cp.async.commit_group;\n"); }
__device__ __forceinline__ void cp_wait1()  { asm volatile("cp.async.wait_group 1;\n" ::: "memory"); }
__device__ __forceinline__ void cp_wait0()  { asm volatile("cp.async.wait_group 0;\n" ::: "memory"); }

__device__ __forceinline__ float silu(float x) { return x / (1.0f + __expf(-x)); }

__global__ void zero_out_kernel(float* out, int n) {
    int i = blockIdx.x * blockDim.x + threadIdx.x;
    if (i < n) out[i] = 0.0f;
}

// W1p word i: q=i&3, lane=(i>>2)&31, ks=(i>>7)&3, nb2=(i>>9)&15, kc=i>>13
// word holds W1[n][k]: n = nb2*16 + (lane>>2) + (q&2?8:0); k = kc*32+ks*8+(lane&3)+(q&1?4:0)
__global__ void pack_w1_kernel(const float* __restrict__ W1) {
    int i = blockIdx.x * blockDim.x + threadIdx.x;
    if (i >= 256 * 1024) return;
    int q = i & 3, lane = (i >> 2) & 31, ks = (i >> 7) & 3, nb2 = (i >> 9) & 15, kc = i >> 13;
    int n = nb2 * 16 + (lane >> 2) + ((q & 2) ? 8 : 0);
    int k = kc * 32 + ks * 8 + (lane & 3) + ((q & 1) ? 4 : 0);
    g_W1p[i] = cvt_tf32(W1[n * 1024 + k]);
}

// W2p: same slotting on permuted k-index kh; original col c = (kh&~7) + 2*(kh&3) + ((kh>>2)&1)
__global__ void pack_w2_kernel(const float* __restrict__ W2) {
    int i = blockIdx.x * blockDim.x + threadIdx.x;
    if (i >= 256 * 256) return;
    int q = i & 3, lane = (i >> 2) & 31, ks = (i >> 7) & 3, nb2 = (i >> 9) & 15, kc = i >> 13;
    int n = nb2 * 16 + (lane >> 2) + ((q & 2) ? 8 : 0);
    int kh = kc * 32 + ks * 8 + (lane & 3) + ((q & 1) ? 4 : 0);
    int c = (kh & ~7) + 2 * (kh & 3) + ((kh >> 2) & 1);
    g_W2p[i] = cvt_tf32(W2[n * 256 + c]);
}

__global__ void __launch_bounds__(NTHREADS, 1)
fused_psm_kernel(const float* __restrict__ ps,
                 const int*   __restrict__ numbers,
                 const int*   __restrict__ batch,
                 const float* __restrict__ Wcomp,
                 const float* __restrict__ Wpsl,
                 const float* __restrict__ Wout,
                 float* __restrict__ out) {
    extern __shared__ char smem[];
    float* sWout = (float*)(smem + OFF_WOUT);
    float* sAtom = (float*)(smem + OFF_SATOM);

    const int tid  = threadIdx.x;
    const int lane = tid & 31;
    const int w    = tid >> 5;
    const int g    = lane >> 2;
    const int t    = lane & 3;
    const long tileBase = (long)blockIdx.x * M_TILE;

    if (tid < 256) sWout[tid] = Wout[tid];
    if (tid < 128) sAtom[tid] = 0.0f;

    // ---- producer mapping: thread owns fragment slots tid and tid+512 ----
    const int mb0 = tid >> 7;           // 0..3
    const int ksp = (tid >> 5) & 3;     // 0..3
    const int rAl = mb0 * 16 + g;       // local rows: rAl, rAl+8, rAl+64, rAl+72
    const long rA = tileBase + rAl;
    const bool vA = rA      < N_ATOMS, vB = rA + 8  < N_ATOMS;
    const bool vC = rA + 64 < N_ATOMS, vD = rA + 72 < N_ATOMS;
    const float* pA = ps + rA * N_FEAT;
    const float* pB = pA + 8L * N_FEAT;
    const float* pC = pA + 64L * N_FEAT;
    const float* pD = pA + 72L * N_FEAT;
    const int kk0 = ksp * 8 + t;        // chunk-local k of "lo"; "hi" = +4

    const uint32_t sB_u32 = (uint32_t)__cvta_generic_to_shared(smem + OFF_B);

    // consumer warp tiling: 4 M-warps x 4 N-warps
    const int wm = w & 3;               // A row block: rows wm*32..+32  (mb = wm*2 + mt)
    const int wn = w >> 2;              // cols wn*64..+64 (nb2 pairs wn*4..+4)

    float acc[2][8][4];
#pragma unroll
    for (int mt = 0; mt < 2; mt++)
#pragma unroll
        for (int nt = 0; nt < 8; nt++)
#pragma unroll
            for (int c = 0; c < 4; c++) acc[mt][nt][c] = 0.0f;

    float pslA = 0.f, pslB = 0.f, pslC = 0.f, pslD = 0.f;
    float rg[2][8];

    // prologue: regs <- chunk 0 ; cp.async B chunk 0 -> buf 0
    {
        int kk = kk0;
        rg[0][0] = vA ? pA[kk] : 0.f;  rg[0][1] = vA ? pA[kk + 4] : 0.f;
        rg[0][2] = vB ? pB[kk] : 0.f;  rg[0][3] = vB ? pB[kk + 4] : 0.f;
        rg[0][4] = vC ? pC[kk] : 0.f;  rg[0][5] = vC ? pC[kk + 4] : 0.f;
        rg[0][6] = vD ? pD[kk] : 0.f;  rg[0][7] = vD ? pD[kk + 4] : 0.f;
#pragma unroll
        for (int j = 0; j < 4; j++) {
            int w16 = tid + j * NTHREADS;
            cp_async16(sB_u32 + w16 * 16, &g_W1p[w16 * 4]);
        }
        cp_commit();
    }

    // =============== GEMM1 ===============
#pragma unroll 2
    for (int kc = 0; kc < CHUNKS1; kc++) {
        const int buf = kc & 1;
        // psl partials on raw fp32
        {
            float wlo = Wpsl[kc * 32 + kk0], whi = Wpsl[kc * 32 + kk0 + 4];
            pslA += rg[buf][0] * wlo + rg[buf][1] * whi;
            pslB += rg[buf][2] * wlo + rg[buf][3] * whi;
            pslC += rg[buf][4] * wlo + rg[buf][5] * whi;
            pslD += rg[buf][6] * wlo + rg[buf][7] * whi;
        }
        // A fragment stores (conflict-free STS.128)
        {
            uint4* As = (uint4*)(smem + OFF_A + buf * 16384);
            As[tid] = make_uint4(cvt_tf32(rg[buf][0]), cvt_tf32(rg[buf][2]),
                                 cvt_tf32(rg[buf][1]), cvt_tf32(rg[buf][3]));
            As[tid + 512] = make_uint4(cvt_tf32(rg[buf][4]), cvt_tf32(rg[buf][6]),
                                       cvt_tf32(rg[buf][5]), cvt_tf32(rg[buf][7]));
        }
        // prefetch next A chunk regs + next B chunk cp.async
        if (kc + 1 < CHUNKS1) {
            int kk = (kc + 1) * 32 + kk0;
            rg[buf ^ 1][0] = vA ? pA[kk] : 0.f;  rg[buf ^ 1][1] = vA ? pA[kk + 4] : 0.f;
            rg[buf ^ 1][2] = vB ? pB[kk] : 0.f;  rg[buf ^ 1][3] = vB ? pB[kk + 4] : 0.f;
            rg[buf ^ 1][4] = vC ? pC[kk] : 0.f;  rg[buf ^ 1][5] = vC ? pC[kk + 4] : 0.f;
            rg[buf ^ 1][6] = vD ? pD[kk] : 0.f;  rg[buf ^ 1][7] = vD ? pD[kk + 4] : 0.f;
            uint32_t dstb = sB_u32 + ((kc + 1) % 3) * 32768;
#pragma unroll
            for (int j = 0; j < 4; j++) {
                int w16 = tid + j * NTHREADS;
                cp_async16(dstb + w16 * 16, &g_W1p[(kc + 1) * 8192 + w16 * 4]);
            }
            cp_commit();
            cp_wait1();
        } else {
            cp_wait0();
        }
        __syncthreads();

        // MMA on buf
        const uint4* As = (const uint4*)(smem + OFF_A + buf * 16384);
        const uint4* Bs = (const uint4*)(smem + OFF_B + (kc % 3) * 32768);
#pragma unroll
        for (int ks = 0; ks < 4; ks++) {
            uint4 av0 = As[((wm * 2 + 0) * 4 + ks) * 32 + lane];
            uint4 av1 = As[((wm * 2 + 1) * 4 + ks) * 32 + lane];
#pragma unroll
            for (int nb = 0; nb < 4; nb++) {
                uint4 bv = Bs[((wn * 4 + nb) * 4 + ks) * 32 + lane];
                uint32_t b0[2] = {bv.x, bv.y}, b1[2] = {bv.z, bv.w};
                mma_tf32(acc[0][2 * nb],     (const uint32_t*)&av0, b0);
                mma_tf32(acc[0][2 * nb + 1], (const uint32_t*)&av0, b1);
                mma_tf32(acc[1][2 * nb],     (const uint32_t*)&av1, b0);
                mma_tf32(acc[1][2 * nb + 1], (const uint32_t*)&av1, b1);
            }
        }
    }
    __syncthreads();   // all GEMM1 MMA reads done before h1 overwrites A bufs

    // psl partial reduce into sAtom
    atomicAdd(&sAtom[rAl],      pslA);
    atomicAdd(&sAtom[rAl + 8],  pslB);
    atomicAdd(&sAtom[rAl + 64], pslC);
    atomicAdd(&sAtom[rAl + 72], pslD);

    // ---- h1 = tf32(silu(acc)) -> GEMM2 A-fragment chunks (σ-permuted k) ----
#pragma unroll
    for (int mt = 0; mt < 2; mt++) {
        const int mb = wm * 2 + mt;
#pragma unroll
        for (int nt = 0; nt < 8; nt++) {
            const int kblk = wn * 8 + nt;            // 0..31
            uint4* H = (uint4*)(smem + OFF_H1 + (kblk >> 2) * 16384);
            H[((mb * 4 + (kblk & 3)) * 32) + lane] =
                make_uint4(cvt_tf32(silu(acc[mt][nt][0])),
                           cvt_tf32(silu(acc[mt][nt][2])),
                           cvt_tf32(silu(acc[mt][nt][1])),
                           cvt_tf32(silu(acc[mt][nt][3])));
            acc[mt][nt][0] = acc[mt][nt][1] = acc[mt][nt][2] = acc[mt][nt][3] = 0.0f;
        }
    }

    // prologue GEMM2: cp B2 chunk 0 -> buf 0
#pragma unroll
    for (int j = 0; j < 4; j++) {
        int w16 = tid + j * NTHREADS;
        cp_async16(sB_u32 + w16 * 16, &g_W2p[w16 * 4]);
    }
    cp_commit();

    // =============== GEMM2 ===============
    for (int c = 0; c < CHUNKS2; c++) {
        if (c + 1 < CHUNKS2) {
            uint32_t dstb = sB_u32 + ((c + 1) % 3) * 32768;
#pragma unroll
            for (int j = 0; j < 4; j++) {
                int w16 = tid + j * NTHREADS;
                cp_async16(dstb + w16 * 16, &g_W2p[(c + 1) * 8192 + w16 * 4]);
            }
            cp_commit();
            cp_wait1();
        } else {
            cp_wait0();
        }
        __syncthreads();

        const uint4* As = (const uint4*)(smem + OFF_H1 + c * 16384);
        const uint4* Bs = (const uint4*)(smem + OFF_B + (c % 3) * 32768);
#pragma unroll
        for (int ks = 0; ks < 4; ks++) {
            uint4 av0 = As[((wm * 2 + 0) * 4 + ks) * 32 + lane];
            uint4 av1 = As[((wm * 2 + 1) * 4 + ks) * 32 + lane];
#pragma unroll
            for (int nb = 0; nb < 4; nb++) {
                uint4 bv = Bs[((wn * 4 + nb) * 4 + ks) * 32 + lane];
                uint32_t b0[2] = {bv.x, bv.y}, b1[2] = {bv.z, bv.w};
                mma_tf32(acc[0][2 * nb],     (const uint32_t*)&av0, b0);
                mma_tf32(acc[0][2 * nb + 1], (const uint32_t*)&av0, b1);
                mma_tf32(acc[1][2 * nb],     (const uint32_t*)&av1, b0);
                mma_tf32(acc[1][2 * nb + 1], (const uint32_t*)&av1, b1);
            }
        }
    }

    // ---- epilogue: psnn = silu(h2) . Wout ----
#pragma unroll
    for (int mt = 0; mt < 2; mt++) {
        float p0 = 0.0f, p1 = 0.0f;
#pragma unroll
        for (int nt = 0; nt < 8; nt++) {
            int col = wn * 64 + nt * 8 + 2 * t;
            float w0 = sWout[col], w1 = sWout[col + 1];
            p0 += silu(acc[mt][nt][0]) * w0 + silu(acc[mt][nt][1]) * w1;
            p1 += silu(acc[mt][nt][2]) * w0 + silu(acc[mt][nt][3]) * w1;
        }
        p0 += __shfl_xor_sync(0xffffffffu, p0, 1);
        p0 += __shfl_xor_sync(0xffffffffu, p0, 2);
        p1 += __shfl_xor_sync(0xffffffffu, p1, 1);
        p1 += __shfl_xor_sync(0xffffffffu, p1, 2);
        if (t == 0) {
            atomicAdd(&sAtom[wm * 32 + mt * 16 + g], p0);
            atomicAdd(&sAtom[wm * 32 + mt * 16 + 8 + g], p1);
        }
    }
    __syncthreads();

    if (tid < M_TILE) {
        long a = tileBase + tid;
        if (a < N_ATOMS) {
            float v = sAtom[tid] + Wcomp[numbers[a]];
            atomicAdd(&out[batch[a]], v);
        }
    }
}

extern "C" void kernel_launch(void* const* d_in, const int* in_sizes, int n_in,
                              void* d_out, int out_size) {
    const float* ps      = (const float*)d_in[0];
    const int*   numbers = (const int*)  d_in[1];
    const int*   batch   = (const int*)  d_in[2];
    const float* Wcomp   = (const float*)d_in[3];
    const float* Wpsl    = (const float*)d_in[4];
    const float* W1      = (const float*)d_in[5];
    const float* W2      = (const float*)d_in[6];
    const float* Wout    = (const float*)d_in[7];
    float* out = (float*)d_out;

    cudaFuncSetAttribute(fused_psm_kernel,
                         cudaFuncAttributeMaxDynamicSharedMemorySize, SMEM_BYTES);

    zero_out_kernel<<<(out_size + 255) / 256, 256>>>(out, out_size);
    pack_w1_kernel<<<(256 * 1024 + 255) / 256, 256>>>(W1);
    pack_w2_kernel<<<(256 * 256 + 255) / 256, 256>>>(W2);

    int grid = (N_ATOMS + M_TILE - 1) / M_TILE;  // 1563
    fused_psm_kernel<<<grid, NTHREADS, SMEM_BYTES>>>(
        ps, numbers, batch, Wcomp, Wpsl, Wout, out);
}

// round 5
// speedup vs baseline: 1.2674x; 1.2674x over previous
#include <cuda_runtime.h>
#include <cstdint>

#define N_ATOMS  200000
#define N_FEAT   1024
#define N_STRUCT 2000
#define NTHREADS 512
#define M_TILE   128
#define CHUNKS1  32
#define CHUNKS2  8

// ---- SMEM layout (bytes) ----
// A rows: 36 floats (144B) stride; B rows: 144B stride; h1 rows: 260 floats (1040B)
#define A_ROW_B    144
#define B_ROW_B    144
#define H1_ROW_B   1040
#define A_BUF_B    18432                 // 128*144
#define B_BUF_B    36864                 // 256*144
#define OFF_B      0                     // 2 bufs: 73728
#define OFF_A      73728                 // 2 bufs: 36864 (aliased inside h1 region)
#define OFF_H1     73728                 // 128*1040 = 133120 -> ends 206848
#define OFF_WPSL   206848                // 4096
#define OFF_WOUT   210944                // 1024
#define OFF_SATOM  211968                // 512
#define SMEM_BYTES 212480

// weights pre-converted to tf32 (rna), natural [n][k] layout
__device__ __align__(16) uint32_t g_W1c[256 * 1024];
__device__ __align__(16) uint32_t g_W2c[256 * 256];

__device__ __forceinline__ uint32_t cvt_tf32(float x) {
    uint32_t r;
    asm("cvt.rna.tf32.f32 %0, %1;" : "=r"(r) : "f"(x));
    return r;
}

__device__ __forceinline__ void mma_tf32(float c[4], const uint32_t a[4], uint32_t b0, uint32_t b1) {
    asm volatile(
        "mma.sync.aligned.m16n8k8.row.col.f32.tf32.tf32.f32 "
        "{%0,%1,%2,%3}, {%4,%5,%6,%7}, {%8,%9}, {%0,%1,%2,%3};\n"
        : "+f"(c[0]), "+f"(c[1]), "+f"(c[2]), "+f"(c[3])
        : "r"(a[0]), "r"(a[1]), "r"(a[2]), "r"(a[3]), "r"(b0), "r"(b1));
}

#define LDM_X4(r, a) \
    asm volatile("ldmatrix.sync.aligned.m8n8.x4.shared.b16 {%0,%1,%2,%3}, [%4];" \
        : "=r"((r)[0]), "=r"((r)[1]), "=r"((r)[2]), "=r"((r)[3]) : "r"(a))

__device__ __forceinline__ void cp_async16(uint32_t saddr, const void* gptr) {
    asm volatile("cp.async.cg.shared.global [%0], [%1], 16;\n" :: "r"(saddr), "l"(gptr));
}
__device__ __forceinline__ void cp_commit() { asm volatile("cp.async.commit_group;\n"); }
__device__ __forceinline__ void cp_wait0()  { asm volatile("cp.async.wait_group 0;\n" ::: "memory"); }

__device__ __forceinline__ float silu(float x) { return x / (1.0f + __expf(-x)); }
__device__ __forceinline__ float uf(uint32_t x) { return __uint_as_float(x); }

__global__ void zero_out_kernel(float* out, int n) {
    int i = blockIdx.x * blockDim.x + threadIdx.x;
    if (i < n) out[i] = 0.0f;
}

__global__ void cvt_weights_kernel(const float* __restrict__ W1,
                                   const float* __restrict__ W2) {
    int i = blockIdx.x * blockDim.x + threadIdx.x;
    if (i < 256 * 1024) g_W1c[i] = cvt_tf32(W1[i]);
    if (i < 256 * 256)  g_W2c[i] = cvt_tf32(W2[i]);
}

__global__ void __launch_bounds__(NTHREADS, 1)
fused_psm_kernel(const float* __restrict__ ps,
                 const int*   __restrict__ numbers,
                 const int*   __restrict__ batch,
                 const float* __restrict__ Wcomp,
                 const float* __restrict__ Wpsl,
                 const float* __restrict__ Wout,
                 float* __restrict__ out) {
    extern __shared__ char smem[];
    const uint32_t sbase = (uint32_t)__cvta_generic_to_shared(smem);
    float* sWpsl = (float*)(smem + OFF_WPSL);
    float* sWout = (float*)(smem + OFF_WOUT);
    float* sAtom = (float*)(smem + OFF_SATOM);

    const int tid  = threadIdx.x;
    const int lane = tid & 31;
    const int w    = tid >> 5;
    const int g    = lane >> 2;
    const int t    = lane & 3;
    const int wm   = w & 3;    // M-warp row group: rows wm*32..+31
    const int wn   = w >> 2;   // N-warp col group: cols wn*64..+63
    const long tileBase = (long)blockIdx.x * M_TILE;

    // ldmatrix lane geometry
    const int tile = lane >> 3, lr = lane & 7;
    const int arow_l = wm * 32 + ((tile & 1) << 3) + lr;   // av0 rows (av1: +16)
    const int acol4  = (tile >> 1) << 2;                   // float offset 0 or 4
    const int brow_l = wn * 64 + ((tile >> 1) << 3) + lr;  // + j2*16
    const int bcol4  = (tile & 1) << 2;

    const uint32_t aAddr0 = sbase + OFF_A + arow_l * A_ROW_B + acol4 * 4;
    const uint32_t bAddr0 = sbase + OFF_B + brow_l * B_ROW_B + bcol4 * 4;
    const uint32_t hAddr0 = sbase + OFF_H1 + arow_l * H1_ROW_B + acol4 * 4;

    if (tid < 256) sWout[tid] = Wout[tid];
    for (int i = tid; i < 1024; i += NTHREADS) sWpsl[i] = Wpsl[i];

    float acc[2][8][4];
#pragma unroll
    for (int mt = 0; mt < 2; mt++)
#pragma unroll
        for (int nt = 0; nt < 8; nt++)
#pragma unroll
            for (int c = 0; c < 4; c++) acc[mt][nt][c] = 0.0f;

    float pslv[4] = {0.f, 0.f, 0.f, 0.f};

    // ---- async chunk loaders ----
    auto load_A = [&](int kc, int b) {
#pragma unroll
        for (int j = 0; j < 2; j++) {
            int idx = tid + j * NTHREADS;          // 0..1023
            int row = idx >> 3, c = idx & 7;
            uint32_t dst = sbase + OFF_A + b * A_BUF_B + row * A_ROW_B + c * 16;
            long arow = tileBase + row;
            if (arow < N_ATOMS)
                cp_async16(dst, ps + arow * (long)N_FEAT + kc * 32 + c * 4);
            else
                *(uint4*)(smem + OFF_A + b * A_BUF_B + row * A_ROW_B + c * 16) =
                    make_uint4(0, 0, 0, 0);
        }
    };
    auto load_B1 = [&](int kc, int b) {
#pragma unroll
        for (int j = 0; j < 4; j++) {
            int idx = tid + j * NTHREADS;          // 0..2047
            int row = idx >> 3, c = idx & 7;
            uint32_t dst = sbase + OFF_B + b * B_BUF_B + row * B_ROW_B + c * 16;
            cp_async16(dst, &g_W1c[row * 1024 + kc * 32 + c * 4]);
        }
    };
    auto load_B2 = [&](int c2, int b) {
#pragma unroll
        for (int j = 0; j < 4; j++) {
            int idx = tid + j * NTHREADS;
            int row = idx >> 3, c = idx & 7;
            uint32_t dst = sbase + OFF_B + b * B_BUF_B + row * B_ROW_B + c * 16;
            cp_async16(dst, &g_W2c[row * 256 + c2 * 32 + c * 4]);
        }
    };

    // prologue: chunk 0
    load_A(0, 0);
    load_B1(0, 0);
    cp_commit();

    // =============== GEMM1: acc += ps_tile x W1^T ===============
    for (int kc = 0; kc < CHUNKS1; kc++) {
        const int buf = kc & 1;
        cp_wait0();
        __syncthreads();
        if (kc + 1 < CHUNKS1) {
            load_A(kc + 1, buf ^ 1);
            load_B1(kc + 1, buf ^ 1);
            cp_commit();
        }

        const uint32_t aA = aAddr0 + buf * A_BUF_B;
        const uint32_t bA = bAddr0 + buf * B_BUF_B;
#pragma unroll
        for (int ks = 0; ks < 4; ks++) {
            uint32_t a0[4], a1[4];
            LDM_X4(a0, aA + ks * 32);
            LDM_X4(a1, aA + ks * 32 + 16 * A_ROW_B);

            if (wn == 0) {   // psl on raw fp32 before cvt
                float wlo = sWpsl[kc * 32 + ks * 8 + t];
                float whi = sWpsl[kc * 32 + ks * 8 + t + 4];
                pslv[0] += uf(a0[0]) * wlo + uf(a0[2]) * whi;
                pslv[1] += uf(a0[1]) * wlo + uf(a0[3]) * whi;
                pslv[2] += uf(a1[0]) * wlo + uf(a1[2]) * whi;
                pslv[3] += uf(a1[1]) * wlo + uf(a1[3]) * whi;
            }
#pragma unroll
            for (int q = 0; q < 4; q++) { a0[q] = cvt_tf32(uf(a0[q])); a1[q] = cvt_tf32(uf(a1[q])); }

#pragma unroll
            for (int j2 = 0; j2 < 4; j2++) {
                uint32_t bb[4];
                LDM_X4(bb, bA + ks * 32 + j2 * (16 * B_ROW_B));
                mma_tf32(acc[0][2 * j2],     a0, bb[0], bb[1]);
                mma_tf32(acc[0][2 * j2 + 1], a0, bb[2], bb[3]);
                mma_tf32(acc[1][2 * j2],     a1, bb[0], bb[1]);
                mma_tf32(acc[1][2 * j2 + 1], a1, bb[2], bb[3]);
            }
        }
    }
    __syncthreads();   // drain GEMM1 smem reads before h1 overwrites A alias

    // GEMM2 B chunk 0 prefetch overlaps h1 write
    load_B2(0, 0);
    cp_commit();

    // psl reduce over t -> sAtom (wn==0 warps own all 128 rows)
    if (wn == 0) {
#pragma unroll
        for (int q = 0; q < 4; q++) {
            pslv[q] += __shfl_xor_sync(0xffffffffu, pslv[q], 1);
            pslv[q] += __shfl_xor_sync(0xffffffffu, pslv[q], 2);
        }
        if (t == 0) {
#pragma unroll
            for (int q = 0; q < 4; q++) sAtom[wm * 32 + q * 8 + g] = pslv[q];
        }
    }

    // h1 = tf32(silu(acc)) -> natural row-major SMEM; reset acc
#pragma unroll
    for (int mt = 0; mt < 2; mt++) {
        int row = wm * 32 + mt * 16 + g;
#pragma unroll
        for (int nt = 0; nt < 8; nt++) {
            int col = wn * 64 + nt * 8 + 2 * t;
            *(uint2*)(smem + OFF_H1 + row * H1_ROW_B + col * 4) =
                make_uint2(cvt_tf32(silu(acc[mt][nt][0])), cvt_tf32(silu(acc[mt][nt][1])));
            *(uint2*)(smem + OFF_H1 + (row + 8) * H1_ROW_B + col * 4) =
                make_uint2(cvt_tf32(silu(acc[mt][nt][2])), cvt_tf32(silu(acc[mt][nt][3])));
            acc[mt][nt][0] = acc[mt][nt][1] = acc[mt][nt][2] = acc[mt][nt][3] = 0.0f;
        }
    }

    // =============== GEMM2: acc += h1 x W2^T ===============
    for (int c = 0; c < CHUNKS2; c++) {
        const int buf = c & 1;
        cp_wait0();
        __syncthreads();
        if (c + 1 < CHUNKS2) {
            load_B2(c + 1, buf ^ 1);
            cp_commit();
        }

        const uint32_t aA = hAddr0 + c * 128;      // c*32 floats
        const uint32_t bA = bAddr0 + buf * B_BUF_B;
#pragma unroll
        for (int ks = 0; ks < 4; ks++) {
            uint32_t a0[4], a1[4];
            LDM_X4(a0, aA + ks * 32);
            LDM_X4(a1, aA + ks * 32 + 16 * H1_ROW_B);
#pragma unroll
            for (int j2 = 0; j2 < 4; j2++) {
                uint32_t bb[4];
                LDM_X4(bb, bA + ks * 32 + j2 * (16 * B_ROW_B));
                mma_tf32(acc[0][2 * j2],     a0, bb[0], bb[1]);
                mma_tf32(acc[0][2 * j2 + 1], a0, bb[2], bb[3]);
                mma_tf32(acc[1][2 * j2],     a1, bb[0], bb[1]);
                mma_tf32(acc[1][2 * j2 + 1], a1, bb[2], bb[3]);
            }
        }
    }

    // ---- epilogue: psnn = silu(h2) . Wout ----
#pragma unroll
    for (int mt = 0; mt < 2; mt++) {
        float p0 = 0.0f, p1 = 0.0f;
#pragma unroll
        for (int nt = 0; nt < 8; nt++) {
            int col = wn * 64 + nt * 8 + 2 * t;
            float w0 = sWout[col], w1 = sWout[col + 1];
            p0 += silu(acc[mt][nt][0]) * w0 + silu(acc[mt][nt][1]) * w1;
            p1 += silu(acc[mt][nt][2]) * w0 + silu(acc[mt][nt][3]) * w1;
        }
        p0 += __shfl_xor_sync(0xffffffffu, p0, 1);
        p0 += __shfl_xor_sync(0xffffffffu, p0, 2);
        p1 += __shfl_xor_sync(0xffffffffu, p1, 1);
        p1 += __shfl_xor_sync(0xffffffffu, p1, 2);
        if (t == 0) {
            atomicAdd(&sAtom[wm * 32 + mt * 16 + g], p0);
            atomicAdd(&sAtom[wm * 32 + mt * 16 + 8 + g], p1);
        }
    }
    __syncthreads();

    if (tid < M_TILE) {
        long a = tileBase + tid;
        if (a < N_ATOMS) {
            float v = sAtom[tid] + Wcomp[numbers[a]];
            atomicAdd(&out[batch[a]], v);
        }
    }
}

extern "C" void kernel_launch(void* const* d_in, const int* in_sizes, int n_in,
                              void* d_out, int out_size) {
    const float* ps      = (const float*)d_in[0];
    const int*   numbers = (const int*)  d_in[1];
    const int*   batch   = (const int*)  d_in[2];
    const float* Wcomp   = (const float*)d_in[3];
    const float* Wpsl    = (const float*)d_in[4];
    const float* W1      = (const float*)d_in[5];
    const float* W2      = (const float*)d_in[6];
    const float* Wout    = (const float*)d_in[7];
    float* out = (float*)d_out;

    cudaFuncSetAttribute(fused_psm_kernel,
                         cudaFuncAttributeMaxDynamicSharedMemorySize, SMEM_BYTES);

    zero_out_kernel<<<(out_size + 255) / 256, 256>>>(out, out_size);
    cvt_weights_kernel<<<(256 * 1024 + 255) / 256, 256>>>(W1, W2);

    int grid = (N_ATOMS + M_TILE - 1) / M_TILE;  // 1563
    fused_psm_kernel<<<grid, NTHREADS, SMEM_BYTES>>>(
        ps, numbers, batch, Wcomp, Wpsl, Wout, out);
}

// round 6
// speedup vs baseline: 1.9105x; 1.5074x over previous
#include <cuda_runtime.h>
#include <cstdint>

#define N_ATOMS  200000
#define N_FEAT   1024
#define N_STRUCT 2000
#define NTHREADS 512
#define M_TILE   128
#define CHUNKS1  16      // K=1024 / 64
#define CHUNKS2  4       // K=256  / 64

// ---- SMEM layout (bytes). fp16 operand tiles, rows padded to 144B (64k+8 pad halves)
#define A_ROW_B    144
#define B_ROW_B    144
#define H1_ROW_B   528                   // 256 + 8 pad halves
#define A_BUF_B    18432                 // 128*144
#define B_BUF_B    36864                 // 256*144
#define OFF_B      0                     // 2 bufs -> 73728
#define OFF_A      73728                 // 2 bufs 36864, aliased inside h1 region
#define OFF_H1     73728                 // 128*528 = 67584 -> ends 141312
#define OFF_WPSL   141312                // 4096
#define OFF_WOUT   145408                // 1024
#define OFF_SATOM  146432                // 512
#define SMEM_BYTES 146944

// weights pre-converted to fp16 (rn), natural [n][k] layout, packed as uint32 pairs
__device__ __align__(16) uint32_t g_W1h[256 * 1024 / 2];
__device__ __align__(16) uint32_t g_W2h[256 * 256 / 2];

__device__ __forceinline__ uint32_t pack_f16x2(float lo, float hi) {
    uint32_t r;
    asm("cvt.rn.f16x2.f32 %0, %1, %2;" : "=r"(r) : "f"(hi), "f"(lo));
    return r;
}

__device__ __forceinline__ void mma_f16(float c[4], const uint32_t a[4], uint32_t b0, uint32_t b1) {
    asm volatile(
        "mma.sync.aligned.m16n8k16.row.col.f32.f16.f16.f32 "
        "{%0,%1,%2,%3}, {%4,%5,%6,%7}, {%8,%9}, {%0,%1,%2,%3};\n"
        : "+f"(c[0]), "+f"(c[1]), "+f"(c[2]), "+f"(c[3])
        : "r"(a[0]), "r"(a[1]), "r"(a[2]), "r"(a[3]), "r"(b0), "r"(b1));
}

#define LDM_X4(r, a) \
    asm volatile("ldmatrix.sync.aligned.m8n8.x4.shared.b16 {%0,%1,%2,%3}, [%4];" \
        : "=r"((r)[0]), "=r"((r)[1]), "=r"((r)[2]), "=r"((r)[3]) : "r"(a))

__device__ __forceinline__ void cp_async16(uint32_t saddr, const void* gptr) {
    asm volatile("cp.async.cg.shared.global [%0], [%1], 16;\n" :: "r"(saddr), "l"(gptr));
}
__device__ __forceinline__ void cp_commit() { asm volatile("cp.async.commit_group;\n"); }
__device__ __forceinline__ void cp_wait0()  { asm volatile("cp.async.wait_group 0;\n" ::: "memory"); }

__device__ __forceinline__ float silu(float x) { return x / (1.0f + __expf(-x)); }

__global__ void zero_out_kernel(float* out, int n) {
    int i = blockIdx.x * blockDim.x + threadIdx.x;
    if (i < n) out[i] = 0.0f;
}

__global__ void cvt_weights_kernel(const float* __restrict__ W1,
                                   const float* __restrict__ W2) {
    int i = blockIdx.x * blockDim.x + threadIdx.x;
    if (i < 256 * 1024 / 2) g_W1h[i] = pack_f16x2(W1[2 * i], W1[2 * i + 1]);
    if (i < 256 * 256 / 2)  g_W2h[i] = pack_f16x2(W2[2 * i], W2[2 * i + 1]);
}

__global__ void __launch_bounds__(NTHREADS, 1)
fused_psm_kernel(const float* __restrict__ ps,
                 const int*   __restrict__ numbers,
                 const int*   __restrict__ batch,
                 const float* __restrict__ Wcomp,
                 const float* __restrict__ Wpsl,
                 const float* __restrict__ Wout,
                 float* __restrict__ out) {
    extern __shared__ char smem[];
    const uint32_t sbase = (uint32_t)__cvta_generic_to_shared(smem);
    float* sWpsl = (float*)(smem + OFF_WPSL);
    float* sWout = (float*)(smem + OFF_WOUT);
    float* sAtom = (float*)(smem + OFF_SATOM);

    const int tid  = threadIdx.x;
    const int lane = tid & 31;
    const int w    = tid >> 5;
    const int g    = lane >> 2;
    const int t    = lane & 3;
    const int wm   = w & 3;    // rows wm*32..+31
    const int wn   = w >> 2;   // cols wn*64..+63
    const long tileBase = (long)blockIdx.x * M_TILE;

    // ldmatrix lane geometry (A/h1 path and B path)
    const int lr = lane & 7;
    const uint32_t aAddr0 = sbase + OFF_A +
        (uint32_t)((wm * 32 + ((lane >> 3) & 1) * 8 + lr) * A_ROW_B + (lane >> 4) * 16);
    const uint32_t hAddr0 = sbase + OFF_H1 +
        (uint32_t)((wm * 32 + ((lane >> 3) & 1) * 8 + lr) * H1_ROW_B + (lane >> 4) * 16);
    const uint32_t bAddr0 = sbase + OFF_B +
        (uint32_t)((wn * 64 + (lane >> 4) * 8 + lr) * B_ROW_B + ((lane >> 3) & 1) * 16);

    if (tid < 256) sWout[tid] = Wout[tid];
    if (tid < 128) sAtom[tid] = 0.0f;
    for (int i = tid; i < 1024; i += NTHREADS) sWpsl[i] = Wpsl[i];

    // producer mapping: thread owns row=tid>>2, 16 consecutive k at (tid&3)*16
    const int prow = tid >> 2;
    const int pt4  = tid & 3;
    const bool pvalid = (tileBase + prow) < (long)N_ATOMS;
    const float* pSrc = ps + (tileBase + prow) * (long)N_FEAT + pt4 * 16;
    const uint32_t aStore = sbase + OFF_A + (uint32_t)(prow * A_ROW_B + pt4 * 32);

    float acc[2][8][4];
#pragma unroll
    for (int mt = 0; mt < 2; mt++)
#pragma unroll
        for (int nt = 0; nt < 8; nt++)
#pragma unroll
            for (int c = 0; c < 4; c++) acc[mt][nt][c] = 0.0f;

    float psl = 0.0f;
    float rg[16];

    auto ldg_A = [&](int kc) {
        if (pvalid) {
            const float4* p = (const float4*)(pSrc + kc * 64);
#pragma unroll
            for (int j = 0; j < 4; j++) {
                float4 v = p[j];
                rg[4 * j] = v.x; rg[4 * j + 1] = v.y; rg[4 * j + 2] = v.z; rg[4 * j + 3] = v.w;
            }
        } else {
#pragma unroll
            for (int j = 0; j < 16; j++) rg[j] = 0.0f;
        }
    };
    auto sts_A = [&](int b) {
        uint32_t pk[8];
#pragma unroll
        for (int j = 0; j < 8; j++) pk[j] = pack_f16x2(rg[2 * j], rg[2 * j + 1]);
        uint32_t d = aStore + b * A_BUF_B;
        asm volatile("st.shared.v4.b32 [%0], {%1,%2,%3,%4};" :: "r"(d),
                     "r"(pk[0]), "r"(pk[1]), "r"(pk[2]), "r"(pk[3]));
        asm volatile("st.shared.v4.b32 [%0], {%1,%2,%3,%4};" :: "r"(d + 16),
                     "r"(pk[4]), "r"(pk[5]), "r"(pk[6]), "r"(pk[7]));
    };
    auto psl_acc = [&](int kc) {
        const float* wp = sWpsl + kc * 64 + pt4 * 16;
#pragma unroll
        for (int j = 0; j < 16; j++) psl += rg[j] * wp[j];
    };
    auto load_B1 = [&](int kc, int b) {
#pragma unroll
        for (int j = 0; j < 4; j++) {
            int idx = tid + j * NTHREADS;          // 0..2047
            int row = idx >> 3, c8 = idx & 7;
            uint32_t dst = sbase + OFF_B + b * B_BUF_B + row * B_ROW_B + c8 * 16;
            cp_async16(dst, &g_W1h[row * 512 + kc * 32 + c8 * 4]);
        }
        cp_commit();
    };
    auto load_B2 = [&](int c2, int b) {
#pragma unroll
        for (int j = 0; j < 4; j++) {
            int idx = tid + j * NTHREADS;
            int row = idx >> 3, c8 = idx & 7;
            uint32_t dst = sbase + OFF_B + b * B_BUF_B + row * B_ROW_B + c8 * 16;
            cp_async16(dst, &g_W2h[row * 128 + c2 * 32 + c8 * 4]);
        }
        cp_commit();
    };

    // ---- prologue: A chunk0 -> buf0 now; B chunk0 in flight; A chunk1 in regs
    ldg_A(0);
    load_B1(0, 0);
    sts_A(0);
    psl_acc(0);
    ldg_A(1);

    // =============== GEMM1 ===============
    for (int kc = 0; kc < CHUNKS1; kc++) {
        const int buf = kc & 1;
        cp_wait0();
        __syncthreads();   // B(kc) arrived; A(kc) STS visible; buf^1 reads drained

        if (kc + 1 < CHUNKS1) {
            sts_A(buf ^ 1);          // A(kc+1) from regs
            psl_acc(kc + 1);
            load_B1(kc + 1, buf ^ 1);
            if (kc + 2 < CHUNKS1) ldg_A(kc + 2);
        }

        const uint32_t aA = aAddr0 + buf * A_BUF_B;
        const uint32_t bA = bAddr0 + buf * B_BUF_B;
#pragma unroll
        for (int ks = 0; ks < 4; ks++) {
            uint32_t a0[4], a1[4];
            LDM_X4(a0, aA + ks * 32);
            LDM_X4(a1, aA + ks * 32 + 16 * A_ROW_B);
#pragma unroll
            for (int np = 0; np < 4; np++) {
                uint32_t bb[4];
                LDM_X4(bb, bA + ks * 32 + np * (16 * B_ROW_B));
                mma_f16(acc[0][2 * np],     a0, bb[0], bb[1]);
                mma_f16(acc[0][2 * np + 1], a0, bb[2], bb[3]);
                mma_f16(acc[1][2 * np],     a1, bb[0], bb[1]);
                mma_f16(acc[1][2 * np + 1], a1, bb[2], bb[3]);
            }
        }
    }
    __syncthreads();   // drain GEMM1 smem reads before h1 overwrites A alias

    // GEMM2 B chunk 0 prefetch overlaps h1 write
    load_B2(0, 0);

    // psl reduce (4 threads per row share a warp quad)
    psl += __shfl_xor_sync(0xffffffffu, psl, 1);
    psl += __shfl_xor_sync(0xffffffffu, psl, 2);
    if (pt4 == 0) sAtom[prow] = psl;

    // h1 = fp16(silu(acc)) -> row-major SMEM; reset acc
#pragma unroll
    for (int mt = 0; mt < 2; mt++) {
        int row = wm * 32 + mt * 16 + g;
#pragma unroll
        for (int nt = 0; nt < 8; nt++) {
            int col = wn * 64 + nt * 8 + 2 * t;
            *(uint32_t*)(smem + OFF_H1 + row * H1_ROW_B + col * 2) =
                pack_f16x2(silu(acc[mt][nt][0]), silu(acc[mt][nt][1]));
            *(uint32_t*)(smem + OFF_H1 + (row + 8) * H1_ROW_B + col * 2) =
                pack_f16x2(silu(acc[mt][nt][2]), silu(acc[mt][nt][3]));
            acc[mt][nt][0] = acc[mt][nt][1] = acc[mt][nt][2] = acc[mt][nt][3] = 0.0f;
        }
    }

    // =============== GEMM2: acc += h1 x W2^T ===============
    for (int c = 0; c < CHUNKS2; c++) {
        const int buf = c & 1;
        cp_wait0();
        __syncthreads();
        if (c + 1 < CHUNKS2) load_B2(c + 1, buf ^ 1);

        const uint32_t aA = hAddr0 + c * 128;      // c*64 halves
        const uint32_t bA = bAddr0 + buf * B_BUF_B;
#pragma unroll
        for (int ks = 0; ks < 4; ks++) {
            uint32_t a0[4], a1[4];
            LDM_X4(a0, aA + ks * 32);
            LDM_X4(a1, aA + ks * 32 + 16 * H1_ROW_B);
#pragma unroll
            for (int np = 0; np < 4; np++) {
                uint32_t bb[4];
                LDM_X4(bb, bA + ks * 32 + np * (16 * B_ROW_B));
                mma_f16(acc[0][2 * np],     a0, bb[0], bb[1]);
                mma_f16(acc[0][2 * np + 1], a0, bb[2], bb[3]);
                mma_f16(acc[1][2 * np],     a1, bb[0], bb[1]);
                mma_f16(acc[1][2 * np + 1], a1, bb[2], bb[3]);
            }
        }
    }

    // ---- epilogue: psnn = silu(h2) . Wout ----
#pragma unroll
    for (int mt = 0; mt < 2; mt++) {
        float p0 = 0.0f, p1 = 0.0f;
#pragma unroll
        for (int nt = 0; nt < 8; nt++) {
            int col = wn * 64 + nt * 8 + 2 * t;
            float w0 = sWout[col], w1 = sWout[col + 1];
            p0 += silu(acc[mt][nt][0]) * w0 + silu(acc[mt][nt][1]) * w1;
            p1 += silu(acc[mt][nt][2]) * w0 + silu(acc[mt][nt][3]) * w1;
        }
        p0 += __shfl_xor_sync(0xffffffffu, p0, 1);
        p0 += __shfl_xor_sync(0xffffffffu, p0, 2);
        p1 += __shfl_xor_sync(0xffffffffu, p1, 1);
        p1 += __shfl_xor_sync(0xffffffffu, p1, 2);
        if (t == 0) {
            atomicAdd(&sAtom[wm * 32 + mt * 16 + g], p0);
            atomicAdd(&sAtom[wm * 32 + mt * 16 + 8 + g], p1);
        }
    }
    __syncthreads();

    if (tid < M_TILE) {
        long a = tileBase + tid;
        if (a < N_ATOMS) {
            float v = sAtom[tid] + Wcomp[numbers[a]];
            atomicAdd(&out[batch[a]], v);
        }
    }
}

extern "C" void kernel_launch(void* const* d_in, const int* in_sizes, int n_in,
                              void* d_out, int out_size) {
    const float* ps      = (const float*)d_in[0];
    const int*   numbers = (const int*)  d_in[1];
    const int*   batch   = (const int*)  d_in[2];
    const float* Wcomp   = (const float*)d_in[3];
    const float* Wpsl    = (const float*)d_in[4];
    const float* W1      = (const float*)d_in[5];
    const float* W2      = (const float*)d_in[6];
    const float* Wout    = (const float*)d_in[7];
    float* out = (float*)d_out;

    cudaFuncSetAttribute(fused_psm_kernel,
                         cudaFuncAttributeMaxDynamicSharedMemorySize, SMEM_BYTES);

    zero_out_kernel<<<(out_size + 255) / 256, 256>>>(out, out_size);
    cvt_weights_kernel<<<(256 * 1024 / 2 + 255) / 256, 256>>>(W1, W2);

    int grid = (N_ATOMS + M_TILE - 1) / M_TILE;  // 1563
    fused_psm_kernel<<<grid, NTHREADS, SMEM_BYTES>>>(
        ps, numbers, batch, Wcomp, Wpsl, Wout, out);
}